// round 15
// baseline (speedup 1.0000x reference)
#include <cuda_runtime.h>
#include <cuda_bf16.h>
#include <math_constants.h>

// Problem dims (fixed by reference setup_inputs)
#define B     128
#define H     400
#define IN    784
#define OUT   10
#define NP    200              // H/2 neuron pairs
#define BG    32               // batches per layer1 block
#define ES    12               // event segments (4 chunks = 64 events each)
#define NW    25               // ceil(784/32) bit words per batch
#define NTHR  (BG * ES)        // 384 threads
#define NCH   25               // 16-leaf chunks in H=400

#define THRESH 0.5f
#define DECAY  0.2f

// Scratch (allocation-free rule: __device__ globals)
__device__ unsigned g_bits[NW * B];   // [word][batch] input spike bitmask
__device__ float    g_spk[B * H];     // h1 spikes as floats
__device__ float    g_pmax[NP * B];   // per-(pair,batch) layer1 max partial
__device__ float    g_pmin[NP * B];

// PDL primitives
__device__ __forceinline__ void pdl_wait() {
    asm volatile("griddepcontrol.wait;" ::: "memory");
}
__device__ __forceinline__ void pdl_launch_dependents() {
    asm volatile("griddepcontrol.launch_dependents;" ::: "memory");
}

// ---- packed f32x2 helpers (2 floats in one 64-bit reg pair) -----------------
typedef unsigned long long P2;

__device__ __forceinline__ P2 p2_pack(float x, float y) {
    P2 r;
    asm("mov.b64 %0, {%1, %2};" : "=l"(r) : "f"(x), "f"(y));
    return r;
}
__device__ __forceinline__ float2 p2_unpack(P2 p) {
    float2 v;
    asm("mov.b64 {%0, %1}, %2;" : "=f"(v.x), "=f"(v.y) : "l"(p));
    return v;
}
__device__ __forceinline__ P2 p2_add(P2 u, P2 v) {
    P2 r;
    asm("add.rn.f32x2 %0, %1, %2;" : "=l"(r) : "l"(u), "l"(v));
    return r;
}

// ---------------------------------------------------------------------------
// Kernel 0: pack input_vec (B x IN, {0,1} floats) into bit words, transposed
// layout g_bits[w*B + b]. One warp per word: single load + ballot.
// Triggers dependent launch at entry: layer1's W1 staging overlaps us.
// ---------------------------------------------------------------------------
__global__ __launch_bounds__(800) void k_pack(const float* __restrict__ input_vec) {
    pdl_launch_dependents();
    int b = blockIdx.x;
    int t = threadIdx.x;
    int w = t >> 5;
    int lane = t & 31;
    float v = (t < IN) ? input_vec[b * IN + t] : 0.0f;
    unsigned m = __ballot_sync(0xffffffffu, v != 0.0f);
    if (lane == 0) g_bits[w * B + b] = m;
}

// ---------------------------------------------------------------------------
// chunk16 (layer 1): 16 consecutive events, 2 neurons. Sign-mask gating
// (bitwise exact), packed prefix qp for per-leaf scalar FMNMX snapshots,
// balanced-16 tree via leaf-level binary counter. Arithmetic per neuron is
// identical to the R13/R14-passing kernels (NC=4 -> NC=2 repackaging only).
// ---------------------------------------------------------------------------
__device__ __forceinline__ P2 chunk16(
    unsigned half, const float2* __restrict__ sW, int ebase,
    P2& qp, float2& mx, float2& mn)
{
    P2 k1, k2, k4, k8, out;
#pragma unroll
    for (int j = 0; j < 16; ++j) {
        int msk = ((int)(half << (31 - j))) >> 31;   // all-ones if bit j set
        float2 w = sW[ebase + j];
        float tx = __int_as_float(msk & __float_as_int(w.x));
        float ty = __int_as_float(msk & __float_as_int(w.y));
        P2 tp = p2_pack(tx, ty);
        qp = p2_add(qp, tp);                         // exact when gated off
        float2 q = p2_unpack(qp);
        mx.x = fmaxf(mx.x, q.x); mx.y = fmaxf(mx.y, q.y);
        mn.x = fminf(mn.x, q.x); mn.y = fminf(mn.y, q.y);
        if ((j & 1) == 0) {
            k1 = tp;
        } else {
            P2 s = p2_add(k1, tp);
            if ((j & 2) == 0) k2 = s;
            else {
                s = p2_add(k2, s);
                if ((j & 4) == 0) k4 = s;
                else {
                    s = p2_add(k4, s);
                    if (j == 7) k8 = s;
                    else out = p2_add(k8, s);        // j == 15
                }
            }
        }
    }
    return out;
}

// ---------------------------------------------------------------------------
// Kernel 1: layer 1. Block = 2 neurons x 32 batches x 12 segments (384 thr).
// __launch_bounds__(384, 3): ~50-reg live set fits 56-reg cap -> occ 3
// (36 warps/SM). Grid = 200 pairs x 4 batch-groups = 800 blocks (1.8 waves).
// PDL: triggers dependents at entry, stages W1 (independent of k_pack), then
// griddepcontrol.wait before touching g_bits.
// Recombination reproduces the R2-verified JAX tree bitwise:
//   t_i = u_{2i} + u_{2i+1};  S = (((t0+t1)+(t2+t3))+(t4+t5)) + L
// Snapshot max/min recombined with running segment-total offsets (approx,
// tol 1e-3; passes at 1.5e-7).
// ---------------------------------------------------------------------------
__global__ __launch_bounds__(NTHR, 3) void k_layer1(
    const float* __restrict__ W1,       // [H][IN]
    const float* __restrict__ h1_mem0,  // [H]
    float* __restrict__ out_h1mem)      // [B][H] (slice of d_out)
{
    __shared__ float2 sW[IN];                 // sW[e] = (w_n0, w_n1)[e]
    __shared__ float2 s_tree[ES][BG];
    __shared__ float2 s_px[ES][BG];
    __shared__ float2 s_pn[ES][BG];
    __shared__ float2 s_L[BG];

    pdl_launch_dependents();

    const int t   = threadIdx.x;
    const int seg = t >> 5;                   // 0..11 (one warp per segment)
    const int bl  = t & 31;                   // local batch
    const int b   = blockIdx.y * BG + bl;     // global batch
    const int n0  = blockIdx.x * 2;           // neuron pair base

    // Prologue (independent of k_pack): stage weights
    for (int i = t; i < 2 * IN; i += NTHR) {
        int c = i / IN;
        int e = i - c * IN;
        ((float*)sW)[e * 2 + c] = W1[(n0 + c) * IN + e];
    }
    pdl_wait();                               // g_bits now visible
    __syncthreads();

    P2 qp = 0ull;
    float2 mx = make_float2(-CUDART_INF_F, -CUDART_INF_F);
    float2 mn = make_float2( CUDART_INF_F,  CUDART_INF_F);
    P2 p1, p2, treeP;

    const int c0 = seg * 4;
#pragma unroll
    for (int wi = 0; wi < 2; ++wi) {
        unsigned word = g_bits[((c0 >> 1) + wi) * B + b];
#pragma unroll
        for (int hsel = 0; hsel < 2; ++hsel) {
            int lc = wi * 2 + hsel;
            unsigned half = hsel ? (word >> 16) : (word & 0xffffu);
            P2 s = chunk16(half, sW, (c0 + lc) * 16, qp, mx, mn);
            if (lc & 1) {
                s = p2_add(p1, s);
                if (lc & 2) treeP = p2_add(p2, s);   // lc == 3
                else p2 = s;                          // lc == 1
            } else p1 = s;
        }
    }
    if (seg == ES - 1) {
        unsigned half = g_bits[24 * B + b] & 0xffffu;
        s_L[bl] = p2_unpack(chunk16(half, sW, 768, qp, mx, mn));
    }
    s_tree[seg][bl] = p2_unpack(treeP);
    s_px[seg][bl]   = mx;
    s_pn[seg][bl]   = mn;
    __syncthreads();

    if (seg == 0) {                           // 32 finalize threads, 1/batch
        const float2 m = make_float2(h1_mem0[n0], h1_mem0[n0 + 1]);

        // Pass 1: snapshot recombination with running offsets
        float2 o   = make_float2(0.f, 0.f);
        float2 gmx = make_float2(-CUDART_INF_F, -CUDART_INF_F);
        float2 gmn = make_float2( CUDART_INF_F,  CUDART_INF_F);
#pragma unroll
        for (int i = 0; i < ES; ++i) {
            float2 tr = s_tree[i][bl];
            float2 px = s_px[i][bl];
            float2 pn = s_pn[i][bl];
            gmx.x = fmaxf(gmx.x, o.x + px.x); gmx.y = fmaxf(gmx.y, o.y + px.y);
            gmn.x = fminf(gmn.x, o.x + pn.x); gmn.y = fminf(gmn.y, o.y + pn.y);
            o.x += tr.x; o.y += tr.y;
        }

        // Pass 2: exact tree recombination t_i = u_{2i}+u_{2i+1};
        // S = (((t0+t1)+(t2+t3))+(t4+t5)) + L
        float2 tt[6];
#pragma unroll
        for (int i = 0; i < 6; ++i) {
            float2 ua = s_tree[2 * i][bl];
            float2 ub = s_tree[2 * i + 1][bl];
            tt[i] = make_float2(ua.x + ub.x, ua.y + ub.y);
        }
        float2 L = s_L[bl];
        float2 f;
        f.x = m.x + ((((tt[0].x + tt[1].x) + (tt[2].x + tt[3].x)) + (tt[4].x + tt[5].x)) + L.x);
        f.y = m.y + ((((tt[0].y + tt[1].y) + (tt[2].y + tt[3].y)) + (tt[4].y + tt[5].y)) + L.y);

        float2 spk, hm;
        spk.x = f.x > THRESH ? 1.0f : 0.0f;  hm.x = f.x > THRESH ? 0.0f : f.x * DECAY;
        spk.y = f.y > THRESH ? 1.0f : 0.0f;  hm.y = f.y > THRESH ? 0.0f : f.y * DECAY;
        *(float2*)(g_spk + b * H + n0) = spk;
        *(float2*)(out_h1mem + b * H + n0) = hm;

        g_pmax[blockIdx.x * B + b] = fmaxf(m.x + gmx.x, m.y + gmx.y);
        g_pmin[blockIdx.x * B + b] = fminf(m.x + gmn.x, m.y + gmn.y);
    }
}

// ---------------------------------------------------------------------------
// Kernel 2: layer 2 + finalize (R13-exact numerics; fold bound NP=200).
// Block = one batch, 256 threads. PDL: stages W2 first, then wait.
// Lane-task = (chunk, neuron): 250 active lanes, 16-leaf chains. 10 finalize
// threads recombine the 25 chunks with the R2/R8-exact binary counter:
//   acc = ((g0 + g1) + g2) + L
// ---------------------------------------------------------------------------
#define L2T 256
__global__ __launch_bounds__(L2T) void k_layer2(
    const float* __restrict__ W2,       // [OUT][H]
    const float* __restrict__ h2_mem0,  // [OUT]
    float* __restrict__ out_h2s,        // [B][OUT]
    float* __restrict__ out_smax,       // [B]
    float* __restrict__ out_smin,       // [B]
    float* __restrict__ out_h2mem)      // [B][OUT]
{
    __shared__ float sW2[OUT][H + 1];   // stride 401 -> conflict-free lanes
    __shared__ float spk[H];
    __shared__ float s_ch[NCH][OUT];
    __shared__ float s_px[NCH][OUT];
    __shared__ float s_pn[NCH][OUT];
    __shared__ float s_fmx[L2T / 32], s_fmn[L2T / 32];
    __shared__ float s_nmx[OUT], s_nmn[OUT];

    const int b = blockIdx.x;
    const int t = threadIdx.x;
    const int w = t >> 5;
    const int lane = t & 31;

    // Prologue (independent of layer1): stage W2
    for (int i = t; i < OUT * H; i += L2T) sW2[i / H][i % H] = W2[i];

    pdl_wait();                         // g_spk / g_pmax now visible

    for (int i = t; i < H; i += L2T) spk[i] = g_spk[b * H + i];

    float fmx = -CUDART_INF_F, fmn = CUDART_INF_F;
    for (int k = t; k < NP; k += L2T) {
        fmx = fmaxf(fmx, g_pmax[k * B + b]);
        fmn = fminf(fmn, g_pmin[k * B + b]);
    }
#pragma unroll
    for (int off = 16; off > 0; off >>= 1) {
        fmx = fmaxf(fmx, __shfl_xor_sync(0xffffffffu, fmx, off));
        fmn = fminf(fmn, __shfl_xor_sync(0xffffffffu, fmn, off));
    }
    if (lane == 0) { s_fmx[w] = fmx; s_fmn[w] = fmn; }

    __syncthreads();

    if (t < NCH * OUT) {
        const int c = t / OUT;
        const int n = t - c * OUT;
        const float* w2 = sW2[n];
        const int ebase = c * 16;
        float q = 0.0f, px = -CUDART_INF_F, pn = CUDART_INF_F;
        float k1, k2, k4, k8, tree;
#pragma unroll
        for (int j = 0; j < 16; ++j) {
            float tv = spk[ebase + j] * w2[ebase + j];   // exact: 0 or w
            q += tv;
            px = fmaxf(px, q);
            pn = fminf(pn, q);
            if ((j & 1) == 0) k1 = tv;
            else {
                float s = k1 + tv;
                if ((j & 2) == 0) k2 = s;
                else {
                    s = k2 + s;
                    if ((j & 4) == 0) k4 = s;
                    else {
                        s = k4 + s;
                        if (j == 7) k8 = s;
                        else tree = k8 + s;              // j == 15
                    }
                }
            }
        }
        s_ch[c][n] = tree;
        s_px[c][n] = px;
        s_pn[c][n] = pn;
    }
    __syncthreads();

    if (t < OUT) {
        const float m0 = h2_mem0[t];
        float o = 0.0f;
        float gmx = -CUDART_INF_F, gmn = CUDART_INF_F;
        float p1, p2, p3, acc;
#pragma unroll
        for (int c = 0; c < 24; ++c) {
            float s = s_ch[c][t];
            gmx = fmaxf(gmx, o + s_px[c][t]);
            gmn = fminf(gmn, o + s_pn[c][t]);
            o += s;
            if (c & 1) { s = p1 + s;
                if (c & 2) { s = p2 + s;
                    if (c & 4) { s = p3 + s; acc = (c == 7) ? s : acc + s; }
                    else p3 = s;
                } else p2 = s;
            } else p1 = s;
        }
        float sL = s_ch[24][t];
        gmx = fmaxf(gmx, o + s_px[24][t]);
        gmn = fminf(gmn, o + s_pn[24][t]);
        float S = acc + sL;                 // ((g0+g1)+g2)+L — exact JAX tree
        float fin = m0 + S;

        s_nmx[t] = m0 + gmx;
        s_nmn[t] = m0 + gmn;
        bool sp = fin > THRESH;
        out_h2s[b * OUT + t]   = sp ? 1.0f : 0.0f;
        out_h2mem[b * OUT + t] = sp ? 0.0f : fin * DECAY;
    }
    __syncthreads();

    if (t == 0) {
        float mxv = s_fmx[0], mnv = s_fmn[0];
#pragma unroll
        for (int i = 1; i < L2T / 32; ++i) {
            mxv = fmaxf(mxv, s_fmx[i]);
            mnv = fminf(mnv, s_fmn[i]);
        }
#pragma unroll
        for (int i = 0; i < OUT; ++i) {
            mxv = fmaxf(mxv, s_nmx[i]);
            mnv = fminf(mnv, s_nmn[i]);
        }
        out_smax[b] = mxv;
        out_smin[b] = mnv;
    }
}

// ---------------------------------------------------------------------------
// Launch. Full PDL chain (launch_dependents at entry of each primary, wait
// in each dependent). Graph-capturable. Output layout = flat concat:
//   h2_spiked [B*OUT] | step_max [B] | step_min [B] | h1_mem [B*H] | h2_mem [B*OUT]
// ---------------------------------------------------------------------------
extern "C" void kernel_launch(void* const* d_in, const int* in_sizes, int n_in,
                              void* d_out, int out_size) {
    const float* input_vec = (const float*)d_in[0];
    const float* W1        = (const float*)d_in[1];
    const float* W2        = (const float*)d_in[2];
    const float* h1_mem0   = (const float*)d_in[3];
    const float* h2_mem0   = (const float*)d_in[4];

    float* out = (float*)d_out;
    float* out_h2s   = out;                            // B*OUT
    float* out_smax  = out + B * OUT;                  // B
    float* out_smin  = out + B * OUT + B;              // B
    float* out_h1mem = out + B * OUT + 2 * B;          // B*H
    float* out_h2mem = out + B * OUT + 2 * B + B * H;  // B*OUT

    cudaLaunchAttribute attr[1];
    attr[0].id = cudaLaunchAttributeProgrammaticStreamSerialization;
    attr[0].val.programmaticStreamSerializationAllowed = 1;

    {
        cudaLaunchConfig_t cfg = {};
        cfg.gridDim  = dim3(B);
        cfg.blockDim = dim3(800);
        cfg.stream   = 0;
        cudaLaunchKernelEx(&cfg, k_pack, input_vec);
    }
    {
        cudaLaunchConfig_t cfg = {};
        cfg.gridDim  = dim3(NP, B / BG);
        cfg.blockDim = dim3(NTHR);
        cfg.stream   = 0;
        cfg.attrs    = attr;
        cfg.numAttrs = 1;
        cudaLaunchKernelEx(&cfg, k_layer1, W1, h1_mem0, out_h1mem);
    }
    {
        cudaLaunchConfig_t cfg = {};
        cfg.gridDim  = dim3(B);
        cfg.blockDim = dim3(L2T);
        cfg.stream   = 0;
        cfg.attrs    = attr;
        cfg.numAttrs = 1;
        cudaLaunchKernelEx(&cfg, k_layer2, W2, h2_mem0,
                           out_h2s, out_smax, out_smin, out_h2mem);
    }
}

// round 17
// speedup vs baseline: 1.1653x; 1.1653x over previous
#include <cuda_runtime.h>
#include <cuda_bf16.h>
#include <math_constants.h>

// Problem dims (fixed by reference setup_inputs)
#define B     128
#define H     400
#define IN    784
#define OUT   10
#define NQ    100              // H/4 neuron quads
#define BG    32               // batches per layer1 block
#define ES    12               // event segments (4 chunks = 64 events each)
#define NW    25               // ceil(784/32) bit words per batch
#define NTHR  (BG * ES)        // 384 threads
#define NCH   25               // 16-leaf chunks in H=400

#define THRESH 0.5f
#define DECAY  0.2f

// Scratch (allocation-free rule: __device__ globals)
__device__ unsigned g_bits[NW * B];   // [word][batch] input spike bitmask
__device__ float    g_spk[B * H];     // h1 spikes as floats
__device__ float    g_pmax[NQ * B];   // per-(quad,batch) layer1 max partial
__device__ float    g_pmin[NQ * B];

// PDL primitives
__device__ __forceinline__ void pdl_wait() {
    asm volatile("griddepcontrol.wait;" ::: "memory");
}
__device__ __forceinline__ void pdl_launch_dependents() {
    asm volatile("griddepcontrol.launch_dependents;" ::: "memory");
}

// ---- packed f32x2 helpers (4 floats in 2x 64-bit regs) ----------------------
struct P4 { unsigned long long a, b; };

__device__ __forceinline__ P4 p4_zero() { P4 r; r.a = 0ull; r.b = 0ull; return r; }

__device__ __forceinline__ P4 p4_pack(float x, float y, float z, float w) {
    P4 r;
    asm("mov.b64 %0, {%2, %3};\n\tmov.b64 %1, {%4, %5};"
        : "=l"(r.a), "=l"(r.b) : "f"(x), "f"(y), "f"(z), "f"(w));
    return r;
}
__device__ __forceinline__ float4 p4_unpack(P4 p) {
    float4 v;
    asm("mov.b64 {%0, %1}, %4;\n\tmov.b64 {%2, %3}, %5;"
        : "=f"(v.x), "=f"(v.y), "=f"(v.z), "=f"(v.w) : "l"(p.a), "l"(p.b));
    return v;
}
__device__ __forceinline__ P4 p4_add(P4 u, P4 v) {
    P4 r;
    asm("add.rn.f32x2 %0, %2, %3;\n\tadd.rn.f32x2 %1, %4, %5;"
        : "=l"(r.a), "=l"(r.b) : "l"(u.a), "l"(v.a), "l"(u.b), "l"(v.b));
    return r;
}

// ---------------------------------------------------------------------------
// Kernel 0: pack input_vec (B x IN, {0,1} floats) into bit words, transposed
// layout g_bits[w*B + b]. One warp per word: single load + ballot.
// Triggers dependent launch at entry: layer1's W1 staging overlaps us.
// ---------------------------------------------------------------------------
__global__ __launch_bounds__(800) void k_pack(const float* __restrict__ input_vec) {
    pdl_launch_dependents();
    int b = blockIdx.x;
    int t = threadIdx.x;
    int w = t >> 5;
    int lane = t & 31;
    float v = (t < IN) ? input_vec[b * IN + t] : 0.0f;
    unsigned m = __ballot_sync(0xffffffffu, v != 0.0f);
    if (lane == 0) g_bits[w * B + b] = m;
}

// ---------------------------------------------------------------------------
// chunk16 (layer 1): 16 consecutive events, 4 neurons. Sign-mask gating
// (bitwise exact), packed prefix qp for per-leaf scalar FMNMX snapshots,
// balanced-16 tree via leaf-level binary counter. R13/R14-exact.
// ---------------------------------------------------------------------------
__device__ __forceinline__ P4 chunk16(
    unsigned half, const float4* __restrict__ sW, int ebase,
    P4& qp, float4& mx, float4& mn)
{
    P4 k1, k2, k4, k8, out;
#pragma unroll
    for (int j = 0; j < 16; ++j) {
        int msk = ((int)(half << (31 - j))) >> 31;   // all-ones if bit j set
        float4 w = sW[ebase + j];
        float tx = __int_as_float(msk & __float_as_int(w.x));
        float ty = __int_as_float(msk & __float_as_int(w.y));
        float tz = __int_as_float(msk & __float_as_int(w.z));
        float tw = __int_as_float(msk & __float_as_int(w.w));
        P4 tp = p4_pack(tx, ty, tz, tw);
        qp = p4_add(qp, tp);                         // exact when gated off
        float4 q = p4_unpack(qp);
        mx.x = fmaxf(mx.x, q.x); mx.y = fmaxf(mx.y, q.y);
        mx.z = fmaxf(mx.z, q.z); mx.w = fmaxf(mx.w, q.w);
        mn.x = fminf(mn.x, q.x); mn.y = fminf(mn.y, q.y);
        mn.z = fminf(mn.z, q.z); mn.w = fminf(mn.w, q.w);
        if ((j & 1) == 0) {
            k1 = tp;
        } else {
            P4 s = p4_add(k1, tp);
            if ((j & 2) == 0) k2 = s;
            else {
                s = p4_add(k2, s);
                if ((j & 4) == 0) k4 = s;
                else {
                    s = p4_add(k4, s);
                    if (j == 7) k8 = s;
                    else out = p4_add(k8, s);        // j == 15
                }
            }
        }
    }
    return out;
}

// ---------------------------------------------------------------------------
// Kernel 1: layer 1 (R14-exact numerics; g_bits loads hoisted). Block =
// 4 neurons x 32 batches x 12 segments (384 threads, occ 2). PDL: triggers
// dependents at entry, stages W1 (independent of k_pack), then wait; then
// ALL bit-words for this thread (2, +1 for seg 11) load back-to-back (MLP)
// before the first chunk16 so the later words' latency hides under compute.
// Recombination reproduces the R2-verified JAX tree bitwise:
//   t_i = u_{2i} + u_{2i+1};  S = (((t0+t1)+(t2+t3))+(t4+t5)) + L
// ---------------------------------------------------------------------------
__global__ __launch_bounds__(NTHR, 2) void k_layer1(
    const float* __restrict__ W1,       // [H][IN]
    const float* __restrict__ h1_mem0,  // [H]
    float* __restrict__ out_h1mem)      // [B][H] (slice of d_out)
{
    __shared__ float4 sW[IN];                 // sW[e] = (w_n0..w_n3)[e]
    __shared__ float4 s_tree[ES][BG];
    __shared__ float4 s_px[ES][BG];
    __shared__ float4 s_pn[ES][BG];
    __shared__ float4 s_L[BG];

    pdl_launch_dependents();

    const int t   = threadIdx.x;
    const int seg = t >> 5;                   // 0..11 (one warp per segment)
    const int bl  = t & 31;                   // local batch
    const int b   = blockIdx.y * BG + bl;     // global batch
    const int n0  = blockIdx.x * 4;           // neuron quad base

    // Prologue (independent of k_pack): stage weights
    for (int i = t; i < 4 * IN; i += NTHR) {
        int c = i / IN;
        int e = i - c * IN;
        ((float*)sW)[e * 4 + c] = W1[(n0 + c) * IN + e];
    }
    pdl_wait();                               // g_bits now visible

    // Hoisted bit-word loads: both segment words (+ leftover for seg 11)
    // issued back-to-back for MLP before any compute consumes them.
    const int c0 = seg * 4;                   // first chunk of this segment
    unsigned word0 = g_bits[(c0 >> 1) * B + b];
    unsigned word1 = g_bits[((c0 >> 1) + 1) * B + b];
    unsigned wordL = 0;
    if (seg == ES - 1) wordL = g_bits[24 * B + b];   // warp-uniform branch

    __syncthreads();

    P4 qp = p4_zero();
    float4 mx = make_float4(-CUDART_INF_F, -CUDART_INF_F, -CUDART_INF_F, -CUDART_INF_F);
    float4 mn = make_float4( CUDART_INF_F,  CUDART_INF_F,  CUDART_INF_F,  CUDART_INF_F);
    P4 p1, p2, treeP;

    {
        // chunks lc = 0..3 from word0/word1 (association identical to R14)
        P4 s0 = chunk16(word0 & 0xffffu, sW, (c0 + 0) * 16, qp, mx, mn);
        p1 = s0;
        P4 s1 = chunk16(word0 >> 16,     sW, (c0 + 1) * 16, qp, mx, mn);
        p2 = p4_add(p1, s1);                       // lc==1 path
        P4 s2 = chunk16(word1 & 0xffffu, sW, (c0 + 2) * 16, qp, mx, mn);
        p1 = s2;
        P4 s3 = chunk16(word1 >> 16,     sW, (c0 + 3) * 16, qp, mx, mn);
        treeP = p4_add(p2, p4_add(p1, s3));        // lc==3: (p2 + (p1 + s))
    }
    if (seg == ES - 1) {
        // leftover chunk 48 (events 768..783): tree separate, snapshots
        // continue seg 11's local prefix.
        s_L[bl] = p4_unpack(chunk16(wordL & 0xffffu, sW, 768, qp, mx, mn));
    }
    s_tree[seg][bl] = p4_unpack(treeP);
    s_px[seg][bl]   = mx;
    s_pn[seg][bl]   = mn;
    __syncthreads();

    if (seg == 0) {                           // 32 finalize threads, 1/batch
        const float4 m = *(const float4*)(h1_mem0 + n0);

        // Pass 1: snapshot recombination with running offsets
        float4 o   = make_float4(0.f, 0.f, 0.f, 0.f);
        float4 gmx = make_float4(-CUDART_INF_F, -CUDART_INF_F, -CUDART_INF_F, -CUDART_INF_F);
        float4 gmn = make_float4( CUDART_INF_F,  CUDART_INF_F,  CUDART_INF_F,  CUDART_INF_F);
#pragma unroll
        for (int i = 0; i < ES; ++i) {
            float4 tr = s_tree[i][bl];
            float4 px = s_px[i][bl];
            float4 pn = s_pn[i][bl];
            gmx.x = fmaxf(gmx.x, o.x + px.x); gmx.y = fmaxf(gmx.y, o.y + px.y);
            gmx.z = fmaxf(gmx.z, o.z + px.z); gmx.w = fmaxf(gmx.w, o.w + px.w);
            gmn.x = fminf(gmn.x, o.x + pn.x); gmn.y = fminf(gmn.y, o.y + pn.y);
            gmn.z = fminf(gmn.z, o.z + pn.z); gmn.w = fminf(gmn.w, o.w + pn.w);
            o.x += tr.x; o.y += tr.y; o.z += tr.z; o.w += tr.w;
        }

        // Pass 2: exact tree recombination t_i = u_{2i}+u_{2i+1};
        // S = (((t0+t1)+(t2+t3))+(t4+t5)) + L
        float4 tt[6];
#pragma unroll
        for (int i = 0; i < 6; ++i) {
            float4 ua = s_tree[2 * i][bl];
            float4 ub = s_tree[2 * i + 1][bl];
            tt[i] = make_float4(ua.x + ub.x, ua.y + ub.y, ua.z + ub.z, ua.w + ub.w);
        }
        float4 L = s_L[bl];
        float4 f;
        f.x = m.x + ((((tt[0].x + tt[1].x) + (tt[2].x + tt[3].x)) + (tt[4].x + tt[5].x)) + L.x);
        f.y = m.y + ((((tt[0].y + tt[1].y) + (tt[2].y + tt[3].y)) + (tt[4].y + tt[5].y)) + L.y);
        f.z = m.z + ((((tt[0].z + tt[1].z) + (tt[2].z + tt[3].z)) + (tt[4].z + tt[5].z)) + L.z);
        f.w = m.w + ((((tt[0].w + tt[1].w) + (tt[2].w + tt[3].w)) + (tt[4].w + tt[5].w)) + L.w);

        float4 spk, hm;
        spk.x = f.x > THRESH ? 1.0f : 0.0f;  hm.x = f.x > THRESH ? 0.0f : f.x * DECAY;
        spk.y = f.y > THRESH ? 1.0f : 0.0f;  hm.y = f.y > THRESH ? 0.0f : f.y * DECAY;
        spk.z = f.z > THRESH ? 1.0f : 0.0f;  hm.z = f.z > THRESH ? 0.0f : f.z * DECAY;
        spk.w = f.w > THRESH ? 1.0f : 0.0f;  hm.w = f.w > THRESH ? 0.0f : f.w * DECAY;
        *(float4*)(g_spk + b * H + n0) = spk;
        *(float4*)(out_h1mem + b * H + n0) = hm;

        g_pmax[blockIdx.x * B + b] =
            fmaxf(fmaxf(m.x + gmx.x, m.y + gmx.y), fmaxf(m.z + gmx.z, m.w + gmx.w));
        g_pmin[blockIdx.x * B + b] =
            fminf(fminf(m.x + gmn.x, m.y + gmn.y), fminf(m.z + gmn.z, m.w + gmn.w));
    }
}

// ---------------------------------------------------------------------------
// Kernel 2: layer 2 + finalize (R14-exact). Block = one batch, 256 threads.
// PDL: stages W2 first, then wait. Lane-task = (chunk, neuron): 250 active
// lanes, 16-leaf chains. 10 finalize threads recombine the 25 chunks with
// the R2/R8-exact binary counter: acc = ((g0 + g1) + g2) + L.
// ---------------------------------------------------------------------------
#define L2T 256
__global__ __launch_bounds__(L2T) void k_layer2(
    const float* __restrict__ W2,       // [OUT][H]
    const float* __restrict__ h2_mem0,  // [OUT]
    float* __restrict__ out_h2s,        // [B][OUT]
    float* __restrict__ out_smax,       // [B]
    float* __restrict__ out_smin,       // [B]
    float* __restrict__ out_h2mem)      // [B][OUT]
{
    __shared__ float sW2[OUT][H + 1];   // stride 401 -> conflict-free lanes
    __shared__ float spk[H];
    __shared__ float s_ch[NCH][OUT];
    __shared__ float s_px[NCH][OUT];
    __shared__ float s_pn[NCH][OUT];
    __shared__ float s_fmx[L2T / 32], s_fmn[L2T / 32];
    __shared__ float s_nmx[OUT], s_nmn[OUT];

    const int b = blockIdx.x;
    const int t = threadIdx.x;
    const int w = t >> 5;
    const int lane = t & 31;

    // Prologue (independent of layer1): stage W2
    for (int i = t; i < OUT * H; i += L2T) sW2[i / H][i % H] = W2[i];

    pdl_wait();                         // g_spk / g_pmax now visible

    for (int i = t; i < H; i += L2T) spk[i] = g_spk[b * H + i];

    float fmx = -CUDART_INF_F, fmn = CUDART_INF_F;
    for (int k = t; k < NQ; k += L2T) {
        fmx = fmaxf(fmx, g_pmax[k * B + b]);
        fmn = fminf(fmn, g_pmin[k * B + b]);
    }
#pragma unroll
    for (int off = 16; off > 0; off >>= 1) {
        fmx = fmaxf(fmx, __shfl_xor_sync(0xffffffffu, fmx, off));
        fmn = fminf(fmn, __shfl_xor_sync(0xffffffffu, fmn, off));
    }
    if (lane == 0) { s_fmx[w] = fmx; s_fmn[w] = fmn; }

    __syncthreads();

    if (t < NCH * OUT) {
        const int c = t / OUT;
        const int n = t - c * OUT;
        const float* w2 = sW2[n];
        const int ebase = c * 16;
        float q = 0.0f, px = -CUDART_INF_F, pn = CUDART_INF_F;
        float k1, k2, k4, k8, tree;
#pragma unroll
        for (int j = 0; j < 16; ++j) {
            float tv = spk[ebase + j] * w2[ebase + j];   // exact: 0 or w
            q += tv;
            px = fmaxf(px, q);
            pn = fminf(pn, q);
            if ((j & 1) == 0) k1 = tv;
            else {
                float s = k1 + tv;
                if ((j & 2) == 0) k2 = s;
                else {
                    s = k2 + s;
                    if ((j & 4) == 0) k4 = s;
                    else {
                        s = k4 + s;
                        if (j == 7) k8 = s;
                        else tree = k8 + s;              // j == 15
                    }
                }
            }
        }
        s_ch[c][n] = tree;
        s_px[c][n] = px;
        s_pn[c][n] = pn;
    }
    __syncthreads();

    if (t < OUT) {
        const float m0 = h2_mem0[t];
        float o = 0.0f;
        float gmx = -CUDART_INF_F, gmn = CUDART_INF_F;
        float p1, p2, p3, acc;
#pragma unroll
        for (int c = 0; c < 24; ++c) {
            float s = s_ch[c][t];
            gmx = fmaxf(gmx, o + s_px[c][t]);
            gmn = fminf(gmn, o + s_pn[c][t]);
            o += s;
            if (c & 1) { s = p1 + s;
                if (c & 2) { s = p2 + s;
                    if (c & 4) { s = p3 + s; acc = (c == 7) ? s : acc + s; }
                    else p3 = s;
                } else p2 = s;
            } else p1 = s;
        }
        float sL = s_ch[24][t];
        gmx = fmaxf(gmx, o + s_px[24][t]);
        gmn = fminf(gmn, o + s_pn[24][t]);
        float S = acc + sL;                 // ((g0+g1)+g2)+L — exact JAX tree
        float fin = m0 + S;

        s_nmx[t] = m0 + gmx;
        s_nmn[t] = m0 + gmn;
        bool sp = fin > THRESH;
        out_h2s[b * OUT + t]   = sp ? 1.0f : 0.0f;
        out_h2mem[b * OUT + t] = sp ? 0.0f : fin * DECAY;
    }
    __syncthreads();

    if (t == 0) {
        float mxv = s_fmx[0], mnv = s_fmn[0];
#pragma unroll
        for (int i = 1; i < L2T / 32; ++i) {
            mxv = fmaxf(mxv, s_fmx[i]);
            mnv = fminf(mnv, s_fmn[i]);
        }
#pragma unroll
        for (int i = 0; i < OUT; ++i) {
            mxv = fmaxf(mxv, s_nmx[i]);
            mnv = fminf(mnv, s_nmn[i]);
        }
        out_smax[b] = mxv;
        out_smin[b] = mnv;
    }
}

// ---------------------------------------------------------------------------
// Launch. Full PDL chain (launch_dependents at entry of each primary, wait
// in each dependent). Graph-capturable. Output layout = flat concat:
//   h2_spiked [B*OUT] | step_max [B] | step_min [B] | h1_mem [B*H] | h2_mem [B*OUT]
// ---------------------------------------------------------------------------
extern "C" void kernel_launch(void* const* d_in, const int* in_sizes, int n_in,
                              void* d_out, int out_size) {
    const float* input_vec = (const float*)d_in[0];
    const float* W1        = (const float*)d_in[1];
    const float* W2        = (const float*)d_in[2];
    const float* h1_mem0   = (const float*)d_in[3];
    const float* h2_mem0   = (const float*)d_in[4];

    float* out = (float*)d_out;
    float* out_h2s   = out;                            // B*OUT
    float* out_smax  = out + B * OUT;                  // B
    float* out_smin  = out + B * OUT + B;              // B
    float* out_h1mem = out + B * OUT + 2 * B;          // B*H
    float* out_h2mem = out + B * OUT + 2 * B + B * H;  // B*OUT

    cudaLaunchAttribute attr[1];
    attr[0].id = cudaLaunchAttributeProgrammaticStreamSerialization;
    attr[0].val.programmaticStreamSerializationAllowed = 1;

    {
        cudaLaunchConfig_t cfg = {};
        cfg.gridDim  = dim3(B);
        cfg.blockDim = dim3(800);
        cfg.stream   = 0;
        cudaLaunchKernelEx(&cfg, k_pack, input_vec);
    }
    {
        cudaLaunchConfig_t cfg = {};
        cfg.gridDim  = dim3(NQ, B / BG);
        cfg.blockDim = dim3(NTHR);
        cfg.stream   = 0;
        cfg.attrs    = attr;
        cfg.numAttrs = 1;
        cudaLaunchKernelEx(&cfg, k_layer1, W1, h1_mem0, out_h1mem);
    }
    {
        cudaLaunchConfig_t cfg = {};
        cfg.gridDim  = dim3(B);
        cfg.blockDim = dim3(L2T);
        cfg.stream   = 0;
        cfg.attrs    = attr;
        cfg.numAttrs = 1;
        cudaLaunchKernelEx(&cfg, k_layer2, W2, h2_mem0,
                           out_h2s, out_smax, out_smin, out_h2mem);
    }
}